// round 15
// baseline (speedup 1.0000x reference)
#include <cuda_runtime.h>
#include <cuda_bf16.h>

#define HIDDEN 768
#define FF     3072
#define NSEQ   128
#define TOKENS 65536
#define TOKB   32
#define SPLIT1 4      // gemm1 K-split: 768/4 = 192 (6 chunks)
#define SPLIT2 32     // gemm2 K-split: 3072/32 = 96 (3 chunks)
#define KC     32     // K floats per chunk
#define RS     80     // smem row stride bytes (32 bf16 = 64B + 16B pad)

// ---------------- scratch (device globals: no allocation) ----------------
__device__ float g_means[NSEQ * HIDDEN];   // pooled means (atomic)
__device__ float g_h1f[NSEQ * FF];         // dense1 fp32 (atomic)
__device__ float g_h2[NSEQ * HIDDEN];      // dense2 out (atomic)

// ---------------- segment mean pooling (proven; at DRAM floor) ----------------
__global__ __launch_bounds__(192) void pool_kernel(const float* __restrict__ hs,
                                                   const int* __restrict__ lens) {
    __shared__ int   sl[NSEQ];
    __shared__ int   segof[TOKB];
    __shared__ float sinv[NSEQ];

    int tid = threadIdx.x;
    if (tid < NSEQ) {
        int l = lens[tid];
        sl[tid]   = l;
        sinv[tid] = 1.0f / (float)l;
    }
    __syncthreads();
    #pragma unroll
    for (int off = 1; off < NSEQ; off <<= 1) {
        int v = 0;
        if (tid < NSEQ && tid >= off) v = sl[tid - off];
        __syncthreads();
        if (tid < NSEQ) sl[tid] += v;
        __syncthreads();
    }

    int t0 = blockIdx.x * TOKB;
    if (tid < TOKB) {
        int t = t0 + tid;
        int lo = 0, hi = NSEQ - 1;
        while (lo < hi) {
            int mid = (lo + hi) >> 1;
            if (sl[mid] > t) hi = mid; else lo = mid + 1;
        }
        segof[tid] = lo;
    }
    __syncthreads();

    const float4* h4 = (const float4*)hs + (size_t)t0 * (HIDDEN / 4) + tid;

    if (segof[0] == segof[TOKB - 1]) {
        int s = segof[0];
        float4 a0 = make_float4(0.f, 0.f, 0.f, 0.f);
        float4 a1 = a0, a2 = a0, a3 = a0;
        #pragma unroll
        for (int i = 0; i < TOKB; i += 8) {
            float4 v0 = h4[(size_t)(i + 0) * (HIDDEN / 4)];
            float4 v1 = h4[(size_t)(i + 1) * (HIDDEN / 4)];
            float4 v2 = h4[(size_t)(i + 2) * (HIDDEN / 4)];
            float4 v3 = h4[(size_t)(i + 3) * (HIDDEN / 4)];
            float4 v4 = h4[(size_t)(i + 4) * (HIDDEN / 4)];
            float4 v5 = h4[(size_t)(i + 5) * (HIDDEN / 4)];
            float4 v6 = h4[(size_t)(i + 6) * (HIDDEN / 4)];
            float4 v7 = h4[(size_t)(i + 7) * (HIDDEN / 4)];
            a0.x += v0.x; a0.y += v0.y; a0.z += v0.z; a0.w += v0.w;
            a1.x += v1.x; a1.y += v1.y; a1.z += v1.z; a1.w += v1.w;
            a2.x += v2.x; a2.y += v2.y; a2.z += v2.z; a2.w += v2.w;
            a3.x += v3.x; a3.y += v3.y; a3.z += v3.z; a3.w += v3.w;
            a0.x += v4.x; a0.y += v4.y; a0.z += v4.z; a0.w += v4.w;
            a1.x += v5.x; a1.y += v5.y; a1.z += v5.z; a1.w += v5.w;
            a2.x += v6.x; a2.y += v6.y; a2.z += v6.z; a2.w += v6.w;
            a3.x += v7.x; a3.y += v7.y; a3.z += v7.z; a3.w += v7.w;
        }
        float inv = sinv[s];
        float* dst = &g_means[s * HIDDEN + tid * 4];
        atomicAdd(dst + 0, (a0.x + a1.x + a2.x + a3.x) * inv);
        atomicAdd(dst + 1, (a0.y + a1.y + a2.y + a3.y) * inv);
        atomicAdd(dst + 2, (a0.z + a1.z + a2.z + a3.z) * inv);
        atomicAdd(dst + 3, (a0.w + a1.w + a2.w + a3.w) * inv);
    } else {
        float4 acc = make_float4(0.f, 0.f, 0.f, 0.f);
        int cur = segof[0];
        #pragma unroll
        for (int i = 0; i < TOKB; i++) {
            float4 v = h4[(size_t)i * (HIDDEN / 4)];
            int s = segof[i];
            if (s != cur) {
                float inv = sinv[cur];
                float* dst = &g_means[cur * HIDDEN + tid * 4];
                atomicAdd(dst + 0, acc.x * inv); atomicAdd(dst + 1, acc.y * inv);
                atomicAdd(dst + 2, acc.z * inv); atomicAdd(dst + 3, acc.w * inv);
                acc = make_float4(0.f, 0.f, 0.f, 0.f);
                cur = s;
            }
            acc.x += v.x; acc.y += v.y; acc.z += v.z; acc.w += v.w;
        }
        float inv = sinv[cur];
        float* dst = &g_means[cur * HIDDEN + tid * 4];
        atomicAdd(dst + 0, acc.x * inv); atomicAdd(dst + 1, acc.y * inv);
        atomicAdd(dst + 2, acc.z * inv); atomicAdd(dst + 3, acc.w * inv);
    }
}

// ---------------- bf16 hi/lo split of a float4 ----------------
__device__ __forceinline__ void split4(float4 v, unsigned long long& hi, unsigned long long& lo) {
    __nv_bfloat16 h0 = __float2bfloat16(v.x), h1 = __float2bfloat16(v.y);
    __nv_bfloat16 h2 = __float2bfloat16(v.z), h3 = __float2bfloat16(v.w);
    __nv_bfloat16 l0 = __float2bfloat16(v.x - __bfloat162float(h0));
    __nv_bfloat16 l1 = __float2bfloat16(v.y - __bfloat162float(h1));
    __nv_bfloat16 l2 = __float2bfloat16(v.z - __bfloat162float(h2));
    __nv_bfloat16 l3 = __float2bfloat16(v.w - __bfloat162float(h3));
    hi = (unsigned long long)__bfloat16_as_ushort(h0)
       | ((unsigned long long)__bfloat16_as_ushort(h1) << 16)
       | ((unsigned long long)__bfloat16_as_ushort(h2) << 32)
       | ((unsigned long long)__bfloat16_as_ushort(h3) << 48);
    lo = (unsigned long long)__bfloat16_as_ushort(l0)
       | ((unsigned long long)__bfloat16_as_ushort(l1) << 16)
       | ((unsigned long long)__bfloat16_as_ushort(l2) << 32)
       | ((unsigned long long)__bfloat16_as_ushort(l3) << 48);
}

#define MMA_BF16(C, A0, A1, A2, A3, B0, B1)                                          \
    asm volatile(                                                                    \
        "mma.sync.aligned.m16n8k16.row.col.f32.bf16.bf16.f32 "                       \
        "{%0,%1,%2,%3}, {%4,%5,%6,%7}, {%8,%9}, {%0,%1,%2,%3};"                      \
        : "+f"((C)[0]), "+f"((C)[1]), "+f"((C)[2]), "+f"((C)[3])                     \
        : "r"(A0), "r"(A1), "r"(A2), "r"(A3), "r"(B0), "r"(B1))

// A-side: 16 fp32 (4 float4) -> bf16 hi/lo smem stores.
__device__ __forceinline__ void store_a_chunk(unsigned char* sm, int SAHI, int SALO,
                                              int ar, int ah, const float4* av) {
    int aoff = ar * RS + ah * 32;
    unsigned long long hi, lo;
    split4(av[0], hi, lo);
    *(unsigned long long*)(sm + SAHI + aoff)      = hi;
    *(unsigned long long*)(sm + SALO + aoff)      = lo;
    split4(av[1], hi, lo);
    *(unsigned long long*)(sm + SAHI + aoff + 8)  = hi;
    *(unsigned long long*)(sm + SALO + aoff + 8)  = lo;
    split4(av[2], hi, lo);
    *(unsigned long long*)(sm + SAHI + aoff + 16) = hi;
    *(unsigned long long*)(sm + SALO + aoff + 16) = lo;
    split4(av[3], hi, lo);
    *(unsigned long long*)(sm + SAHI + aoff + 24) = hi;
    *(unsigned long long*)(sm + SALO + aoff + 24) = lo;
}

// ====== GEMM1: g_h1f += means @ W1^T.  N-tile 32, K-split 4 -> 384 CTAs ======
__global__ __launch_bounds__(256, 3) void gemm1_kernel(const float* __restrict__ W1) {
    __shared__ __align__(128) unsigned char sm[25600];
    const int SAHI = 0, SALO = 10240, SBHI = 20480, SBLO = 23040;

    int tid = threadIdx.x, wid = tid >> 5, lane = tid & 31;
    int g = lane >> 2, tg = lane & 3;
    int wm = wid >> 1, wn = wid & 1;
    int m0 = wm * 32, nb = wn * 16;
    int n0 = blockIdx.x * 32;
    int k0 = blockIdx.y * (6 * KC);                  // 192 K per split

    int ar = tid >> 1, ah = tid & 1;     // A: row 0..127, 16-float half
    int brr = tid >> 3, bq = tid & 7;    // B: row 0..31, float4 idx 0..7

    float c[2][2][4];
    #pragma unroll
    for (int i = 0; i < 2; i++)
        #pragma unroll
        for (int j = 0; j < 2; j++)
            #pragma unroll
            for (int r = 0; r < 4; r++) c[i][j][r] = 0.f;

    const float* pA = g_means + (size_t)ar * HIDDEN + k0 + ah * 16;
    const float* pB = W1 + (size_t)(n0 + brr) * HIDDEN + k0 + bq * 4;

    float4 av[4];
    #pragma unroll
    for (int t = 0; t < 4; t++) av[t] = ((const float4*)pA)[t];
    float4 bv = *(const float4*)pB;

    for (int ch = 0; ch < 6; ch++) {
        store_a_chunk(sm, SAHI, SALO, ar, ah, av);
        {
            unsigned long long hi, lo;
            split4(bv, hi, lo);
            int boff = brr * RS + bq * 8;
            *(unsigned long long*)(sm + SBHI + boff) = hi;
            *(unsigned long long*)(sm + SBLO + boff) = lo;
        }
        __syncthreads();

        if (ch + 1 < 6) {
            int kk = (ch + 1) * KC;
            #pragma unroll
            for (int t = 0; t < 4; t++) av[t] = ((const float4*)(pA + kk))[t];
            bv = *(const float4*)(pB + kk);
        }

        #pragma unroll
        for (int ks = 0; ks < 2; ks++) {
            unsigned Ah[2][4], Al[2][4], Bh[2][2], Bl[2][2];
            #pragma unroll
            for (int i = 0; i < 2; i++) {
                int off = (m0 + i * 16 + g) * RS + ks * 32 + tg * 4;
                Ah[i][0] = *(const unsigned*)(sm + SAHI + off);
                Ah[i][1] = *(const unsigned*)(sm + SAHI + off + 8 * RS);
                Ah[i][2] = *(const unsigned*)(sm + SAHI + off + 16);
                Ah[i][3] = *(const unsigned*)(sm + SAHI + off + 8 * RS + 16);
                Al[i][0] = *(const unsigned*)(sm + SALO + off);
                Al[i][1] = *(const unsigned*)(sm + SALO + off + 8 * RS);
                Al[i][2] = *(const unsigned*)(sm + SALO + off + 16);
                Al[i][3] = *(const unsigned*)(sm + SALO + off + 8 * RS + 16);
            }
            #pragma unroll
            for (int j = 0; j < 2; j++) {
                int off = (nb + j * 8 + g) * RS + ks * 32 + tg * 4;
                Bh[j][0] = *(const unsigned*)(sm + SBHI + off);
                Bh[j][1] = *(const unsigned*)(sm + SBHI + off + 16);
                Bl[j][0] = *(const unsigned*)(sm + SBLO + off);
                Bl[j][1] = *(const unsigned*)(sm + SBLO + off + 16);
            }
            #pragma unroll
            for (int i = 0; i < 2; i++)
                #pragma unroll
                for (int j = 0; j < 2; j++) {
                    MMA_BF16(c[i][j], Ah[i][0], Ah[i][1], Ah[i][2], Ah[i][3], Bh[j][0], Bh[j][1]);
                    MMA_BF16(c[i][j], Ah[i][0], Ah[i][1], Ah[i][2], Ah[i][3], Bl[j][0], Bl[j][1]);
                    MMA_BF16(c[i][j], Al[i][0], Al[i][1], Al[i][2], Al[i][3], Bh[j][0], Bh[j][1]);
                }
        }
        __syncthreads();
    }

    #pragma unroll
    for (int i = 0; i < 2; i++) {
        int R0 = m0 + i * 16 + g, R1 = R0 + 8;
        #pragma unroll
        for (int j = 0; j < 2; j++) {
            int Cc = n0 + nb + j * 8 + tg * 2;
            atomicAdd(&g_h1f[(size_t)R0 * FF + Cc],     c[i][j][0]);
            atomicAdd(&g_h1f[(size_t)R0 * FF + Cc + 1], c[i][j][1]);
            atomicAdd(&g_h1f[(size_t)R1 * FF + Cc],     c[i][j][2]);
            atomicAdd(&g_h1f[(size_t)R1 * FF + Cc + 1], c[i][j][3]);
        }
    }
}

// ====== GEMM2: g_h2 += h1 @ W2^T.  N-tile 64, K-split 32 -> 384 CTAs ======
__global__ __launch_bounds__(256, 3) void gemm2_kernel(const float* __restrict__ W2) {
    __shared__ __align__(128) unsigned char sm[30720];
    const int SAHI = 0, SALO = 10240, SBHI = 20480, SBLO = 25600;

    int tid = threadIdx.x, wid = tid >> 5, lane = tid & 31;
    int g = lane >> 2, tg = lane & 3;
    int wm = wid >> 1, wn = wid & 1;
    int m0 = wm * 32, nb = wn * 32;
    int n0 = blockIdx.x * 64;
    int k0 = blockIdx.y * (3 * KC);                  // 96 K per split

    int ar = tid >> 1, ah = tid & 1;
    int br[2], bq[2];
    #pragma unroll
    for (int t = 0; t < 2; t++) { int idx = tid + t * 256; br[t] = idx >> 3; bq[t] = idx & 7; }

    float c[2][4][4];
    #pragma unroll
    for (int i = 0; i < 2; i++)
        #pragma unroll
        for (int j = 0; j < 4; j++)
            #pragma unroll
            for (int r = 0; r < 4; r++) c[i][j][r] = 0.f;

    const float* pA = g_h1f + (size_t)ar * FF + k0 + ah * 16;

    float4 av[4];
    #pragma unroll
    for (int t = 0; t < 4; t++) av[t] = ((const float4*)pA)[t];
    float4 bv[2];
    #pragma unroll
    for (int t = 0; t < 2; t++)
        bv[t] = *(const float4*)(W2 + (size_t)(n0 + br[t]) * FF + k0 + bq[t] * 4);

    for (int ch = 0; ch < 3; ch++) {
        store_a_chunk(sm, SAHI, SALO, ar, ah, av);
        #pragma unroll
        for (int t = 0; t < 2; t++) {
            unsigned long long hi, lo;
            split4(bv[t], hi, lo);
            int boff = br[t] * RS + bq[t] * 8;
            *(unsigned long long*)(sm + SBHI + boff) = hi;
            *(unsigned long long*)(sm + SBLO + boff) = lo;
        }
        __syncthreads();

        if (ch + 1 < 3) {
            int kk = (ch + 1) * KC;
            #pragma unroll
            for (int t = 0; t < 4; t++) av[t] = ((const float4*)(pA + kk))[t];
            #pragma unroll
            for (int t = 0; t < 2; t++)
                bv[t] = *(const float4*)(W2 + (size_t)(n0 + br[t]) * FF + k0 + kk + bq[t] * 4);
        }

        #pragma unroll
        for (int ks = 0; ks < 2; ks++) {
            unsigned Ah[2][4], Al[2][4], Bh[4][2], Bl[4][2];
            #pragma unroll
            for (int i = 0; i < 2; i++) {
                int off = (m0 + i * 16 + g) * RS + ks * 32 + tg * 4;
                Ah[i][0] = *(const unsigned*)(sm + SAHI + off);
                Ah[i][1] = *(const unsigned*)(sm + SAHI + off + 8 * RS);
                Ah[i][2] = *(const unsigned*)(sm + SAHI + off + 16);
                Ah[i][3] = *(const unsigned*)(sm + SAHI + off + 8 * RS + 16);
                Al[i][0] = *(const unsigned*)(sm + SALO + off);
                Al[i][1] = *(const unsigned*)(sm + SALO + off + 8 * RS);
                Al[i][2] = *(const unsigned*)(sm + SALO + off + 16);
                Al[i][3] = *(const unsigned*)(sm + SALO + off + 8 * RS + 16);
            }
            #pragma unroll
            for (int j = 0; j < 4; j++) {
                int off = (nb + j * 8 + g) * RS + ks * 32 + tg * 4;
                Bh[j][0] = *(const unsigned*)(sm + SBHI + off);
                Bh[j][1] = *(const unsigned*)(sm + SBHI + off + 16);
                Bl[j][0] = *(const unsigned*)(sm + SBLO + off);
                Bl[j][1] = *(const unsigned*)(sm + SBLO + off + 16);
            }
            #pragma unroll
            for (int i = 0; i < 2; i++)
                #pragma unroll
                for (int j = 0; j < 4; j++) {
                    MMA_BF16(c[i][j], Ah[i][0], Ah[i][1], Ah[i][2], Ah[i][3], Bh[j][0], Bh[j][1]);
                    MMA_BF16(c[i][j], Ah[i][0], Ah[i][1], Ah[i][2], Ah[i][3], Bl[j][0], Bl[j][1]);
                    MMA_BF16(c[i][j], Al[i][0], Al[i][1], Al[i][2], Al[i][3], Bh[j][0], Bh[j][1]);
                }
        }
        __syncthreads();
    }

    #pragma unroll
    for (int i = 0; i < 2; i++) {
        int R0 = m0 + i * 16 + g, R1 = R0 + 8;
        #pragma unroll
        for (int j = 0; j < 4; j++) {
            int Cc = n0 + nb + j * 8 + tg * 2;
            atomicAdd(&g_h2[(size_t)R0 * HIDDEN + Cc],     c[i][j][0]);
            atomicAdd(&g_h2[(size_t)R0 * HIDDEN + Cc + 1], c[i][j][1]);
            atomicAdd(&g_h2[(size_t)R1 * HIDDEN + Cc],     c[i][j][2]);
            atomicAdd(&g_h2[(size_t)R1 * HIDDEN + Cc + 1], c[i][j][3]);
        }
    }
}

// ---------------- L2 normalize rows ----------------
__global__ __launch_bounds__(192) void norm_kernel(float* __restrict__ out) {
    int s = blockIdx.x, tid = threadIdx.x;   // one float4 per thread
    float4 acc = ((const float4*)(g_h2 + s * HIDDEN))[tid];
    float ss = acc.x * acc.x + acc.y * acc.y + acc.z * acc.z + acc.w * acc.w;

    __shared__ float red[6];
    #pragma unroll
    for (int o = 16; o > 0; o >>= 1) ss += __shfl_xor_sync(0xffffffffu, ss, o);
    if ((tid & 31) == 0) red[tid >> 5] = ss;
    __syncthreads();
    __shared__ float sInv;
    if (tid == 0) {
        float tot = 0.f;
        #pragma unroll
        for (int w = 0; w < 6; w++) tot += red[w];
        sInv = 1.0f / fmaxf(sqrtf(tot), 1e-12f);
    }
    __syncthreads();
    float inv = sInv;
    float4 r = make_float4(acc.x * inv, acc.y * inv, acc.z * inv, acc.w * inv);
    ((float4*)(out + s * HIDDEN))[tid] = r;
}

// ---------------- launch ----------------
extern "C" void kernel_launch(void* const* d_in, const int* in_sizes, int n_in,
                              void* d_out, int out_size) {
    const float* hs   = (const float*)d_in[0];   // [65536, 768] fp32
    const int*   lens = (const int*)  d_in[1];   // [128] int32
    const float* W1   = (const float*)d_in[2];   // [3072, 768] fp32
    const float* W2   = (const float*)d_in[3];   // [768, 3072] fp32
    float* out = (float*)d_out;                  // [128, 768] fp32

    void *pMeans = 0, *pH1f = 0, *pH2 = 0;
    cudaGetSymbolAddress(&pMeans, g_means);
    cudaGetSymbolAddress(&pH1f,   g_h1f);
    cudaGetSymbolAddress(&pH2,    g_h2);
    cudaMemsetAsync(pMeans, 0, NSEQ * HIDDEN * sizeof(float));
    cudaMemsetAsync(pH1f,   0, NSEQ * FF     * sizeof(float));
    cudaMemsetAsync(pH2,    0, NSEQ * HIDDEN * sizeof(float));

    pool_kernel<<<TOKENS / TOKB, 192>>>(hs, lens);
    gemm1_kernel<<<dim3(FF / 32, SPLIT1), 256>>>(W1);
    gemm2_kernel<<<dim3(HIDDEN / 64, SPLIT2), 256>>>(W2);
    norm_kernel<<<NSEQ, 192>>>(out);
}

// round 16
// speedup vs baseline: 1.3779x; 1.3779x over previous
#include <cuda_runtime.h>
#include <cuda_bf16.h>

#define HIDDEN 768
#define FF     3072
#define NSEQ   128
#define TOKENS 65536
#define TOKB   32
#define SPLIT1 4      // gemm1 K-split: 768/4 = 192 (6 chunks)
#define SPLIT2 32     // gemm2 K-split: 3072/32 = 96 (3 chunks)
#define KC     32     // K floats per chunk
#define RS     80     // smem row stride bytes (32 bf16 = 64B + 16B pad; 16B-aligned)

// ---------------- scratch (device globals: no allocation) ----------------
__device__ float g_means[NSEQ * HIDDEN];   // pooled means (atomic)
__device__ float g_h1f[NSEQ * FF];         // dense1 fp32 (atomic)
__device__ float g_h2[NSEQ * HIDDEN];      // dense2 out (atomic)

// ---------------- segment mean pooling (proven; at DRAM floor) ----------------
__global__ __launch_bounds__(192) void pool_kernel(const float* __restrict__ hs,
                                                   const int* __restrict__ lens) {
    __shared__ int   sl[NSEQ];
    __shared__ int   segof[TOKB];
    __shared__ float sinv[NSEQ];

    int tid = threadIdx.x;
    if (tid < NSEQ) {
        int l = lens[tid];
        sl[tid]   = l;
        sinv[tid] = 1.0f / (float)l;
    }
    __syncthreads();
    #pragma unroll
    for (int off = 1; off < NSEQ; off <<= 1) {
        int v = 0;
        if (tid < NSEQ && tid >= off) v = sl[tid - off];
        __syncthreads();
        if (tid < NSEQ) sl[tid] += v;
        __syncthreads();
    }

    int t0 = blockIdx.x * TOKB;
    if (tid < TOKB) {
        int t = t0 + tid;
        int lo = 0, hi = NSEQ - 1;
        while (lo < hi) {
            int mid = (lo + hi) >> 1;
            if (sl[mid] > t) hi = mid; else lo = mid + 1;
        }
        segof[tid] = lo;
    }
    __syncthreads();

    const float4* h4 = (const float4*)hs + (size_t)t0 * (HIDDEN / 4) + tid;

    if (segof[0] == segof[TOKB - 1]) {
        int s = segof[0];
        float4 a0 = make_float4(0.f, 0.f, 0.f, 0.f);
        float4 a1 = a0, a2 = a0, a3 = a0;
        #pragma unroll
        for (int i = 0; i < TOKB; i += 8) {
            float4 v0 = h4[(size_t)(i + 0) * (HIDDEN / 4)];
            float4 v1 = h4[(size_t)(i + 1) * (HIDDEN / 4)];
            float4 v2 = h4[(size_t)(i + 2) * (HIDDEN / 4)];
            float4 v3 = h4[(size_t)(i + 3) * (HIDDEN / 4)];
            float4 v4 = h4[(size_t)(i + 4) * (HIDDEN / 4)];
            float4 v5 = h4[(size_t)(i + 5) * (HIDDEN / 4)];
            float4 v6 = h4[(size_t)(i + 6) * (HIDDEN / 4)];
            float4 v7 = h4[(size_t)(i + 7) * (HIDDEN / 4)];
            a0.x += v0.x; a0.y += v0.y; a0.z += v0.z; a0.w += v0.w;
            a1.x += v1.x; a1.y += v1.y; a1.z += v1.z; a1.w += v1.w;
            a2.x += v2.x; a2.y += v2.y; a2.z += v2.z; a2.w += v2.w;
            a3.x += v3.x; a3.y += v3.y; a3.z += v3.z; a3.w += v3.w;
            a0.x += v4.x; a0.y += v4.y; a0.z += v4.z; a0.w += v4.w;
            a1.x += v5.x; a1.y += v5.y; a1.z += v5.z; a1.w += v5.w;
            a2.x += v6.x; a2.y += v6.y; a2.z += v6.z; a2.w += v6.w;
            a3.x += v7.x; a3.y += v7.y; a3.z += v7.z; a3.w += v7.w;
        }
        float inv = sinv[s];
        float* dst = &g_means[s * HIDDEN + tid * 4];
        atomicAdd(dst + 0, (a0.x + a1.x + a2.x + a3.x) * inv);
        atomicAdd(dst + 1, (a0.y + a1.y + a2.y + a3.y) * inv);
        atomicAdd(dst + 2, (a0.z + a1.z + a2.z + a3.z) * inv);
        atomicAdd(dst + 3, (a0.w + a1.w + a2.w + a3.w) * inv);
    } else {
        float4 acc = make_float4(0.f, 0.f, 0.f, 0.f);
        int cur = segof[0];
        #pragma unroll
        for (int i = 0; i < TOKB; i++) {
            float4 v = h4[(size_t)i * (HIDDEN / 4)];
            int s = segof[i];
            if (s != cur) {
                float inv = sinv[cur];
                float* dst = &g_means[cur * HIDDEN + tid * 4];
                atomicAdd(dst + 0, acc.x * inv); atomicAdd(dst + 1, acc.y * inv);
                atomicAdd(dst + 2, acc.z * inv); atomicAdd(dst + 3, acc.w * inv);
                acc = make_float4(0.f, 0.f, 0.f, 0.f);
                cur = s;
            }
            acc.x += v.x; acc.y += v.y; acc.z += v.z; acc.w += v.w;
        }
        float inv = sinv[cur];
        float* dst = &g_means[cur * HIDDEN + tid * 4];
        atomicAdd(dst + 0, acc.x * inv); atomicAdd(dst + 1, acc.y * inv);
        atomicAdd(dst + 2, acc.z * inv); atomicAdd(dst + 3, acc.w * inv);
    }
}

// ---------------- bf16 hi/lo split of a float4 ----------------
__device__ __forceinline__ void split4(float4 v, unsigned long long& hi, unsigned long long& lo) {
    __nv_bfloat16 h0 = __float2bfloat16(v.x), h1 = __float2bfloat16(v.y);
    __nv_bfloat16 h2 = __float2bfloat16(v.z), h3 = __float2bfloat16(v.w);
    __nv_bfloat16 l0 = __float2bfloat16(v.x - __bfloat162float(h0));
    __nv_bfloat16 l1 = __float2bfloat16(v.y - __bfloat162float(h1));
    __nv_bfloat16 l2 = __float2bfloat16(v.z - __bfloat162float(h2));
    __nv_bfloat16 l3 = __float2bfloat16(v.w - __bfloat162float(h3));
    hi = (unsigned long long)__bfloat16_as_ushort(h0)
       | ((unsigned long long)__bfloat16_as_ushort(h1) << 16)
       | ((unsigned long long)__bfloat16_as_ushort(h2) << 32)
       | ((unsigned long long)__bfloat16_as_ushort(h3) << 48);
    lo = (unsigned long long)__bfloat16_as_ushort(l0)
       | ((unsigned long long)__bfloat16_as_ushort(l1) << 16)
       | ((unsigned long long)__bfloat16_as_ushort(l2) << 32)
       | ((unsigned long long)__bfloat16_as_ushort(l3) << 48);
}

#define MMA_BF16(C, A0, A1, A2, A3, B0, B1)                                          \
    asm volatile(                                                                    \
        "mma.sync.aligned.m16n8k16.row.col.f32.bf16.bf16.f32 "                       \
        "{%0,%1,%2,%3}, {%4,%5,%6,%7}, {%8,%9}, {%0,%1,%2,%3};"                      \
        : "+f"((C)[0]), "+f"((C)[1]), "+f"((C)[2]), "+f"((C)[3])                     \
        : "r"(A0), "r"(A1), "r"(A2), "r"(A3), "r"(B0), "r"(B1))

// ldmatrix x4: loads 4 m8n8 bf16 fragments (one per 8-lane group address)
__device__ __forceinline__ void ldm_x4(unsigned& r0, unsigned& r1, unsigned& r2, unsigned& r3,
                                       const void* p) {
    unsigned addr = (unsigned)__cvta_generic_to_shared(p);
    asm volatile("ldmatrix.sync.aligned.m8n8.x4.shared.b16 {%0,%1,%2,%3}, [%4];"
                 : "=r"(r0), "=r"(r1), "=r"(r2), "=r"(r3) : "r"(addr));
}

// A-side: 16 fp32 (4 float4) -> bf16 hi/lo smem stores.
__device__ __forceinline__ void store_a_chunk(unsigned char* sm, int SAHI, int SALO,
                                              int ar, int ah, const float4* av) {
    int aoff = ar * RS + ah * 32;
    unsigned long long hi, lo;
    split4(av[0], hi, lo);
    *(unsigned long long*)(sm + SAHI + aoff)      = hi;
    *(unsigned long long*)(sm + SALO + aoff)      = lo;
    split4(av[1], hi, lo);
    *(unsigned long long*)(sm + SAHI + aoff + 8)  = hi;
    *(unsigned long long*)(sm + SALO + aoff + 8)  = lo;
    split4(av[2], hi, lo);
    *(unsigned long long*)(sm + SAHI + aoff + 16) = hi;
    *(unsigned long long*)(sm + SALO + aoff + 16) = lo;
    split4(av[3], hi, lo);
    *(unsigned long long*)(sm + SAHI + aoff + 24) = hi;
    *(unsigned long long*)(sm + SALO + aoff + 24) = lo;
}

// ====== GEMM1: g_h1f += means @ W1^T.  N-tile 32, K-split 4 -> 384 CTAs ======
__global__ __launch_bounds__(256) void gemm1_kernel(const float* __restrict__ W1) {
    __shared__ __align__(128) unsigned char sm[25600];
    const int SAHI = 0, SALO = 10240, SBHI = 20480, SBLO = 23040;

    int tid = threadIdx.x, wid = tid >> 5, lane = tid & 31;
    int g = lane >> 2, tg = lane & 3;
    int wm = wid >> 1, wn = wid & 1;
    int m0 = wm * 32, nb = wn * 16;
    int n0 = blockIdx.x * 32;
    int k0 = blockIdx.y * (6 * KC);                  // 192 K per split

    // ldmatrix per-lane offsets
    int lrow = lane & 7;                 // row within 8x8 matrix
    int amOff = ((lane >> 3) & 1) * 8 + lrow;   // A: m offset within 16-row frag
    int akOff = (lane >> 4) * 16;               // A: k-byte offset (0 or 16)
    int bnOff = (lane >> 4) * 8 + lrow;         // B: n offset within 16-row pair
    int bkOff = ((lane >> 3) & 1) * 16;         // B: k-byte offset

    int ar = tid >> 1, ah = tid & 1;
    int brr = tid >> 3, bq = tid & 7;

    float c[2][2][4];
    #pragma unroll
    for (int i = 0; i < 2; i++)
        #pragma unroll
        for (int j = 0; j < 2; j++)
            #pragma unroll
            for (int r = 0; r < 4; r++) c[i][j][r] = 0.f;

    const float* pA = g_means + (size_t)ar * HIDDEN + k0 + ah * 16;
    const float* pB = W1 + (size_t)(n0 + brr) * HIDDEN + k0 + bq * 4;

    float4 av[4];
    #pragma unroll
    for (int t = 0; t < 4; t++) av[t] = ((const float4*)pA)[t];
    float4 bv = *(const float4*)pB;

    for (int ch = 0; ch < 6; ch++) {
        store_a_chunk(sm, SAHI, SALO, ar, ah, av);
        {
            unsigned long long hi, lo;
            split4(bv, hi, lo);
            int boff = brr * RS + bq * 8;
            *(unsigned long long*)(sm + SBHI + boff) = hi;
            *(unsigned long long*)(sm + SBLO + boff) = lo;
        }
        __syncthreads();

        if (ch + 1 < 6) {
            int kk = (ch + 1) * KC;
            #pragma unroll
            for (int t = 0; t < 4; t++) av[t] = ((const float4*)(pA + kk))[t];
            bv = *(const float4*)(pB + kk);
        }

        #pragma unroll
        for (int ks = 0; ks < 2; ks++) {
            unsigned Ah[2][4], Al[2][4], Bh[2][2], Bl[2][2];
            #pragma unroll
            for (int i = 0; i < 2; i++) {
                int off = (m0 + i * 16 + amOff) * RS + ks * 32 + akOff;
                ldm_x4(Ah[i][0], Ah[i][1], Ah[i][2], Ah[i][3], sm + SAHI + off);
                ldm_x4(Al[i][0], Al[i][1], Al[i][2], Al[i][3], sm + SALO + off);
            }
            {
                int off = (nb + bnOff) * RS + ks * 32 + bkOff;
                ldm_x4(Bh[0][0], Bh[0][1], Bh[1][0], Bh[1][1], sm + SBHI + off);
                ldm_x4(Bl[0][0], Bl[0][1], Bl[1][0], Bl[1][1], sm + SBLO + off);
            }
            #pragma unroll
            for (int i = 0; i < 2; i++)
                #pragma unroll
                for (int j = 0; j < 2; j++) {
                    MMA_BF16(c[i][j], Ah[i][0], Ah[i][1], Ah[i][2], Ah[i][3], Bh[j][0], Bh[j][1]);
                    MMA_BF16(c[i][j], Ah[i][0], Ah[i][1], Ah[i][2], Ah[i][3], Bl[j][0], Bl[j][1]);
                    MMA_BF16(c[i][j], Al[i][0], Al[i][1], Al[i][2], Al[i][3], Bh[j][0], Bh[j][1]);
                }
        }
        __syncthreads();
    }

    #pragma unroll
    for (int i = 0; i < 2; i++) {
        int R0 = m0 + i * 16 + g, R1 = R0 + 8;
        #pragma unroll
        for (int j = 0; j < 2; j++) {
            int Cc = n0 + nb + j * 8 + tg * 2;
            atomicAdd(&g_h1f[(size_t)R0 * FF + Cc],     c[i][j][0]);
            atomicAdd(&g_h1f[(size_t)R0 * FF + Cc + 1], c[i][j][1]);
            atomicAdd(&g_h1f[(size_t)R1 * FF + Cc],     c[i][j][2]);
            atomicAdd(&g_h1f[(size_t)R1 * FF + Cc + 1], c[i][j][3]);
        }
    }
}

// ====== GEMM2: g_h2 += h1 @ W2^T.  N-tile 64, K-split 32 -> 384 CTAs ======
__global__ __launch_bounds__(256) void gemm2_kernel(const float* __restrict__ W2) {
    __shared__ __align__(128) unsigned char sm[30720];
    const int SAHI = 0, SALO = 10240, SBHI = 20480, SBLO = 25600;

    int tid = threadIdx.x, wid = tid >> 5, lane = tid & 31;
    int g = lane >> 2, tg = lane & 3;
    int wm = wid >> 1, wn = wid & 1;
    int m0 = wm * 32, nb = wn * 32;
    int n0 = blockIdx.x * 64;
    int k0 = blockIdx.y * (3 * KC);                  // 96 K per split

    int lrow = lane & 7;
    int amOff = ((lane >> 3) & 1) * 8 + lrow;
    int akOff = (lane >> 4) * 16;
    int bnOff = (lane >> 4) * 8 + lrow;
    int bkOff = ((lane >> 3) & 1) * 16;

    int ar = tid >> 1, ah = tid & 1;
    int br[2], bq[2];
    #pragma unroll
    for (int t = 0; t < 2; t++) { int idx = tid + t * 256; br[t] = idx >> 3; bq[t] = idx & 7; }

    float c[2][4][4];
    #pragma unroll
    for (int i = 0; i < 2; i++)
        #pragma unroll
        for (int j = 0; j < 4; j++)
            #pragma unroll
            for (int r = 0; r < 4; r++) c[i][j][r] = 0.f;

    const float* pA = g_h1f + (size_t)ar * FF + k0 + ah * 16;

    float4 av[4];
    #pragma unroll
    for (int t = 0; t < 4; t++) av[t] = ((const float4*)pA)[t];
    float4 bv[2];
    #pragma unroll
    for (int t = 0; t < 2; t++)
        bv[t] = *(const float4*)(W2 + (size_t)(n0 + br[t]) * FF + k0 + bq[t] * 4);

    for (int ch = 0; ch < 3; ch++) {
        store_a_chunk(sm, SAHI, SALO, ar, ah, av);
        #pragma unroll
        for (int t = 0; t < 2; t++) {
            unsigned long long hi, lo;
            split4(bv[t], hi, lo);
            int boff = br[t] * RS + bq[t] * 8;
            *(unsigned long long*)(sm + SBHI + boff) = hi;
            *(unsigned long long*)(sm + SBLO + boff) = lo;
        }
        __syncthreads();

        if (ch + 1 < 3) {
            int kk = (ch + 1) * KC;
            #pragma unroll
            for (int t = 0; t < 4; t++) av[t] = ((const float4*)(pA + kk))[t];
            #pragma unroll
            for (int t = 0; t < 2; t++)
                bv[t] = *(const float4*)(W2 + (size_t)(n0 + br[t]) * FF + k0 + kk + bq[t] * 4);
        }

        #pragma unroll
        for (int ks = 0; ks < 2; ks++) {
            unsigned Ah[2][4], Al[2][4], Bh[4][2], Bl[4][2];
            #pragma unroll
            for (int i = 0; i < 2; i++) {
                int off = (m0 + i * 16 + amOff) * RS + ks * 32 + akOff;
                ldm_x4(Ah[i][0], Ah[i][1], Ah[i][2], Ah[i][3], sm + SAHI + off);
                ldm_x4(Al[i][0], Al[i][1], Al[i][2], Al[i][3], sm + SALO + off);
            }
            #pragma unroll
            for (int jb = 0; jb < 4; jb += 2) {
                int off = (nb + jb * 8 + bnOff) * RS + ks * 32 + bkOff;
                ldm_x4(Bh[jb][0], Bh[jb][1], Bh[jb + 1][0], Bh[jb + 1][1], sm + SBHI + off);
                ldm_x4(Bl[jb][0], Bl[jb][1], Bl[jb + 1][0], Bl[jb + 1][1], sm + SBLO + off);
            }
            #pragma unroll
            for (int i = 0; i < 2; i++)
                #pragma unroll
                for (int j = 0; j < 4; j++) {
                    MMA_BF16(c[i][j], Ah[i][0], Ah[i][1], Ah[i][2], Ah[i][3], Bh[j][0], Bh[j][1]);
                    MMA_BF16(c[i][j], Ah[i][0], Ah[i][1], Ah[i][2], Ah[i][3], Bl[j][0], Bl[j][1]);
                    MMA_BF16(c[i][j], Al[i][0], Al[i][1], Al[i][2], Al[i][3], Bh[j][0], Bh[j][1]);
                }
        }
        __syncthreads();
    }

    #pragma unroll
    for (int i = 0; i < 2; i++) {
        int R0 = m0 + i * 16 + g, R1 = R0 + 8;
        #pragma unroll
        for (int j = 0; j < 4; j++) {
            int Cc = n0 + nb + j * 8 + tg * 2;
            atomicAdd(&g_h2[(size_t)R0 * HIDDEN + Cc],     c[i][j][0]);
            atomicAdd(&g_h2[(size_t)R0 * HIDDEN + Cc + 1], c[i][j][1]);
            atomicAdd(&g_h2[(size_t)R1 * HIDDEN + Cc],     c[i][j][2]);
            atomicAdd(&g_h2[(size_t)R1 * HIDDEN + Cc + 1], c[i][j][3]);
        }
    }
}

// ---------------- L2 normalize rows ----------------
__global__ __launch_bounds__(192) void norm_kernel(float* __restrict__ out) {
    int s = blockIdx.x, tid = threadIdx.x;   // one float4 per thread
    float4 acc = ((const float4*)(g_h2 + s * HIDDEN))[tid];
    float ss = acc.x * acc.x + acc.y * acc.y + acc.z * acc.z + acc.w * acc.w;

    __shared__ float red[6];
    #pragma unroll
    for (int o = 16; o > 0; o >>= 1) ss += __shfl_xor_sync(0xffffffffu, ss, o);
    if ((tid & 31) == 0) red[tid >> 5] = ss;
    __syncthreads();
    __shared__ float sInv;
    if (tid == 0) {
        float tot = 0.f;
        #pragma unroll
        for (int w = 0; w < 6; w++) tot += red[w];
        sInv = 1.0f / fmaxf(sqrtf(tot), 1e-12f);
    }
    __syncthreads();
    float inv = sInv;
    float4 r = make_float4(acc.x * inv, acc.y * inv, acc.z * inv, acc.w * inv);
    ((float4*)(out + s * HIDDEN))[tid] = r;
}

// ---------------- launch ----------------
extern "C" void kernel_launch(void* const* d_in, const int* in_sizes, int n_in,
                              void* d_out, int out_size) {
    const float* hs   = (const float*)d_in[0];   // [65536, 768] fp32
    const int*   lens = (const int*)  d_in[1];   // [128] int32
    const float* W1   = (const float*)d_in[2];   // [3072, 768] fp32
    const float* W2   = (const float*)d_in[3];   // [768, 3072] fp32
    float* out = (float*)d_out;                  // [128, 768] fp32

    void *pMeans = 0, *pH1f = 0, *pH2 = 0;
    cudaGetSymbolAddress(&pMeans, g_means);
    cudaGetSymbolAddress(&pH1f,   g_h1f);
    cudaGetSymbolAddress(&pH2,    g_h2);
    cudaMemsetAsync(pMeans, 0, NSEQ * HIDDEN * sizeof(float));
    cudaMemsetAsync(pH1f,   0, NSEQ * FF     * sizeof(float));
    cudaMemsetAsync(pH2,    0, NSEQ * HIDDEN * sizeof(float));

    pool_kernel<<<TOKENS / TOKB, 192>>>(hs, lens);
    gemm1_kernel<<<dim3(FF / 32, SPLIT1), 256>>>(W1);
    gemm2_kernel<<<dim3(HIDDEN / 64, SPLIT2), 256>>>(W2);
    norm_kernel<<<NSEQ, 192>>>(out);
}

// round 17
// speedup vs baseline: 1.4138x; 1.0261x over previous
#include <cuda_runtime.h>
#include <cuda_bf16.h>

#define HIDDEN 768
#define FF     3072
#define NSEQ   128
#define TOKENS 65536
#define TOKB   32
#define SPLIT1 4      // gemm1 K-split: 768/4 = 192 (6 chunks)
#define SPLIT2 32     // gemm2 K-split: 3072/32 = 96 (3 chunks)
#define KC     32     // K floats per chunk
#define RS     80     // smem row stride bytes (32 bf16 = 64B + 16B pad; 16B-aligned)

#define G1_BUF 25600  // gemm1 per-buffer smem bytes
#define G2_BUF 30720  // gemm2 per-buffer smem bytes

// ---------------- scratch (device globals: no allocation) ----------------
__device__ float g_means[NSEQ * HIDDEN];   // pooled means (atomic)
__device__ float g_h1f[NSEQ * FF];         // dense1 fp32 (atomic; zeroed by pool)
__device__ float g_h2[NSEQ * HIDDEN];      // dense2 out (atomic; zeroed by gemm1)

// ---------------- segment mean pooling (proven; at DRAM floor) ----------------
__global__ __launch_bounds__(192) void pool_kernel(const float* __restrict__ hs,
                                                   const int* __restrict__ lens) {
    __shared__ int   sl[NSEQ];
    __shared__ int   segof[TOKB];
    __shared__ float sinv[NSEQ];

    int tid = threadIdx.x;

    // fused zero of g_h1f: 2048 blocks x 192 threads == NSEQ*FF elements exactly
    g_h1f[(size_t)blockIdx.x * 192 + tid] = 0.0f;

    if (tid < NSEQ) {
        int l = lens[tid];
        sl[tid]   = l;
        sinv[tid] = 1.0f / (float)l;
    }
    __syncthreads();
    #pragma unroll
    for (int off = 1; off < NSEQ; off <<= 1) {
        int v = 0;
        if (tid < NSEQ && tid >= off) v = sl[tid - off];
        __syncthreads();
        if (tid < NSEQ) sl[tid] += v;
        __syncthreads();
    }

    int t0 = blockIdx.x * TOKB;
    if (tid < TOKB) {
        int t = t0 + tid;
        int lo = 0, hi = NSEQ - 1;
        while (lo < hi) {
            int mid = (lo + hi) >> 1;
            if (sl[mid] > t) hi = mid; else lo = mid + 1;
        }
        segof[tid] = lo;
    }
    __syncthreads();

    const float4* h4 = (const float4*)hs + (size_t)t0 * (HIDDEN / 4) + tid;

    if (segof[0] == segof[TOKB - 1]) {
        int s = segof[0];
        float4 a0 = make_float4(0.f, 0.f, 0.f, 0.f);
        float4 a1 = a0, a2 = a0, a3 = a0;
        #pragma unroll
        for (int i = 0; i < TOKB; i += 8) {
            float4 v0 = h4[(size_t)(i + 0) * (HIDDEN / 4)];
            float4 v1 = h4[(size_t)(i + 1) * (HIDDEN / 4)];
            float4 v2 = h4[(size_t)(i + 2) * (HIDDEN / 4)];
            float4 v3 = h4[(size_t)(i + 3) * (HIDDEN / 4)];
            float4 v4 = h4[(size_t)(i + 4) * (HIDDEN / 4)];
            float4 v5 = h4[(size_t)(i + 5) * (HIDDEN / 4)];
            float4 v6 = h4[(size_t)(i + 6) * (HIDDEN / 4)];
            float4 v7 = h4[(size_t)(i + 7) * (HIDDEN / 4)];
            a0.x += v0.x; a0.y += v0.y; a0.z += v0.z; a0.w += v0.w;
            a1.x += v1.x; a1.y += v1.y; a1.z += v1.z; a1.w += v1.w;
            a2.x += v2.x; a2.y += v2.y; a2.z += v2.z; a2.w += v2.w;
            a3.x += v3.x; a3.y += v3.y; a3.z += v3.z; a3.w += v3.w;
            a0.x += v4.x; a0.y += v4.y; a0.z += v4.z; a0.w += v4.w;
            a1.x += v5.x; a1.y += v5.y; a1.z += v5.z; a1.w += v5.w;
            a2.x += v6.x; a2.y += v6.y; a2.z += v6.z; a2.w += v6.w;
            a3.x += v7.x; a3.y += v7.y; a3.z += v7.z; a3.w += v7.w;
        }
        float inv = sinv[s];
        float* dst = &g_means[s * HIDDEN + tid * 4];
        atomicAdd(dst + 0, (a0.x + a1.x + a2.x + a3.x) * inv);
        atomicAdd(dst + 1, (a0.y + a1.y + a2.y + a3.y) * inv);
        atomicAdd(dst + 2, (a0.z + a1.z + a2.z + a3.z) * inv);
        atomicAdd(dst + 3, (a0.w + a1.w + a2.w + a3.w) * inv);
    } else {
        float4 acc = make_float4(0.f, 0.f, 0.f, 0.f);
        int cur = segof[0];
        #pragma unroll
        for (int i = 0; i < TOKB; i++) {
            float4 v = h4[(size_t)i * (HIDDEN / 4)];
            int s = segof[i];
            if (s != cur) {
                float inv = sinv[cur];
                float* dst = &g_means[cur * HIDDEN + tid * 4];
                atomicAdd(dst + 0, acc.x * inv); atomicAdd(dst + 1, acc.y * inv);
                atomicAdd(dst + 2, acc.z * inv); atomicAdd(dst + 3, acc.w * inv);
                acc = make_float4(0.f, 0.f, 0.f, 0.f);
                cur = s;
            }
            acc.x += v.x; acc.y += v.y; acc.z += v.z; acc.w += v.w;
        }
        float inv = sinv[cur];
        float* dst = &g_means[cur * HIDDEN + tid * 4];
        atomicAdd(dst + 0, acc.x * inv); atomicAdd(dst + 1, acc.y * inv);
        atomicAdd(dst + 2, acc.z * inv); atomicAdd(dst + 3, acc.w * inv);
    }
}

// ---------------- bf16 hi/lo split of a float4 ----------------
__device__ __forceinline__ void split4(float4 v, unsigned long long& hi, unsigned long long& lo) {
    __nv_bfloat16 h0 = __float2bfloat16(v.x), h1 = __float2bfloat16(v.y);
    __nv_bfloat16 h2 = __float2bfloat16(v.z), h3 = __float2bfloat16(v.w);
    __nv_bfloat16 l0 = __float2bfloat16(v.x - __bfloat162float(h0));
    __nv_bfloat16 l1 = __float2bfloat16(v.y - __bfloat162float(h1));
    __nv_bfloat16 l2 = __float2bfloat16(v.z - __bfloat162float(h2));
    __nv_bfloat16 l3 = __float2bfloat16(v.w - __bfloat162float(h3));
    hi = (unsigned long long)__bfloat16_as_ushort(h0)
       | ((unsigned long long)__bfloat16_as_ushort(h1) << 16)
       | ((unsigned long long)__bfloat16_as_ushort(h2) << 32)
       | ((unsigned long long)__bfloat16_as_ushort(h3) << 48);
    lo = (unsigned long long)__bfloat16_as_ushort(l0)
       | ((unsigned long long)__bfloat16_as_ushort(l1) << 16)
       | ((unsigned long long)__bfloat16_as_ushort(l2) << 32)
       | ((unsigned long long)__bfloat16_as_ushort(l3) << 48);
}

#define MMA_BF16(C, A0, A1, A2, A3, B0, B1)                                          \
    asm volatile(                                                                    \
        "mma.sync.aligned.m16n8k16.row.col.f32.bf16.bf16.f32 "                       \
        "{%0,%1,%2,%3}, {%4,%5,%6,%7}, {%8,%9}, {%0,%1,%2,%3};"                      \
        : "+f"((C)[0]), "+f"((C)[1]), "+f"((C)[2]), "+f"((C)[3])                     \
        : "r"(A0), "r"(A1), "r"(A2), "r"(A3), "r"(B0), "r"(B1))

__device__ __forceinline__ void ldm_x4(unsigned& r0, unsigned& r1, unsigned& r2, unsigned& r3,
                                       const void* p) {
    unsigned addr = (unsigned)__cvta_generic_to_shared(p);
    asm volatile("ldmatrix.sync.aligned.m8n8.x4.shared.b16 {%0,%1,%2,%3}, [%4];"
                 : "=r"(r0), "=r"(r1), "=r"(r2), "=r"(r3) : "r"(addr));
}

// A-side: 16 fp32 (4 float4) -> bf16 hi/lo smem stores.
__device__ __forceinline__ void store_a_chunk(unsigned char* sm, int SAHI, int SALO,
                                              int ar, int ah, const float4* av) {
    int aoff = ar * RS + ah * 32;
    unsigned long long hi, lo;
    split4(av[0], hi, lo);
    *(unsigned long long*)(sm + SAHI + aoff)      = hi;
    *(unsigned long long*)(sm + SALO + aoff)      = lo;
    split4(av[1], hi, lo);
    *(unsigned long long*)(sm + SAHI + aoff + 8)  = hi;
    *(unsigned long long*)(sm + SALO + aoff + 8)  = lo;
    split4(av[2], hi, lo);
    *(unsigned long long*)(sm + SAHI + aoff + 16) = hi;
    *(unsigned long long*)(sm + SALO + aoff + 16) = lo;
    split4(av[3], hi, lo);
    *(unsigned long long*)(sm + SAHI + aoff + 24) = hi;
    *(unsigned long long*)(sm + SALO + aoff + 24) = lo;
}

// ====== GEMM1: g_h1f += means @ W1^T.  Double-buffered, 1 barrier/chunk ======
__global__ __launch_bounds__(256) void gemm1_kernel(const float* __restrict__ W1) {
    extern __shared__ __align__(128) unsigned char smd[];
    const int SAHI = 0, SALO = 10240, SBHI = 20480, SBLO = 23040;

    int tid = threadIdx.x, wid = tid >> 5, lane = tid & 31;
    int g = lane >> 2, tg = lane & 3;
    int wm = wid >> 1, wn = wid & 1;
    int m0 = wm * 32, nb = wn * 16;
    int n0 = blockIdx.x * 32;
    int k0 = blockIdx.y * (6 * KC);

    // fused zero of g_h2: 384 CTAs x 256 threads == NSEQ*HIDDEN exactly
    g_h2[(size_t)(blockIdx.y * gridDim.x + blockIdx.x) * 256 + tid] = 0.0f;

    int lrow = lane & 7;
    int amOff = ((lane >> 3) & 1) * 8 + lrow;
    int akOff = (lane >> 4) * 16;
    int bnOff = (lane >> 4) * 8 + lrow;
    int bkOff = ((lane >> 3) & 1) * 16;

    int ar = tid >> 1, ah = tid & 1;
    int brr = tid >> 3, bq = tid & 7;

    float c[2][2][4];
    #pragma unroll
    for (int i = 0; i < 2; i++)
        #pragma unroll
        for (int j = 0; j < 2; j++)
            #pragma unroll
            for (int r = 0; r < 4; r++) c[i][j][r] = 0.f;

    const float* pA = g_means + (size_t)ar * HIDDEN + k0 + ah * 16;
    const float* pB = W1 + (size_t)(n0 + brr) * HIDDEN + k0 + bq * 4;

    float4 av[4];
    #pragma unroll
    for (int t = 0; t < 4; t++) av[t] = ((const float4*)pA)[t];
    float4 bv = *(const float4*)pB;

    for (int ch = 0; ch < 6; ch++) {
        unsigned char* sm = smd + (ch & 1) * G1_BUF;
        store_a_chunk(sm, SAHI, SALO, ar, ah, av);
        {
            unsigned long long hi, lo;
            split4(bv, hi, lo);
            int boff = brr * RS + bq * 8;
            *(unsigned long long*)(sm + SBHI + boff) = hi;
            *(unsigned long long*)(sm + SBLO + boff) = lo;
        }
        __syncthreads();     // single barrier: double buffer protects next store

        if (ch + 1 < 6) {
            int kk = (ch + 1) * KC;
            #pragma unroll
            for (int t = 0; t < 4; t++) av[t] = ((const float4*)(pA + kk))[t];
            bv = *(const float4*)(pB + kk);
        }

        #pragma unroll
        for (int ks = 0; ks < 2; ks++) {
            unsigned Ah[2][4], Al[2][4], Bh[2][2], Bl[2][2];
            #pragma unroll
            for (int i = 0; i < 2; i++) {
                int off = (m0 + i * 16 + amOff) * RS + ks * 32 + akOff;
                ldm_x4(Ah[i][0], Ah[i][1], Ah[i][2], Ah[i][3], sm + SAHI + off);
                ldm_x4(Al[i][0], Al[i][1], Al[i][2], Al[i][3], sm + SALO + off);
            }
            {
                int off = (nb + bnOff) * RS + ks * 32 + bkOff;
                ldm_x4(Bh[0][0], Bh[0][1], Bh[1][0], Bh[1][1], sm + SBHI + off);
                ldm_x4(Bl[0][0], Bl[0][1], Bl[1][0], Bl[1][1], sm + SBLO + off);
            }
            #pragma unroll
            for (int i = 0; i < 2; i++)
                #pragma unroll
                for (int j = 0; j < 2; j++) {
                    MMA_BF16(c[i][j], Ah[i][0], Ah[i][1], Ah[i][2], Ah[i][3], Bh[j][0], Bh[j][1]);
                    MMA_BF16(c[i][j], Ah[i][0], Ah[i][1], Ah[i][2], Ah[i][3], Bl[j][0], Bl[j][1]);
                    MMA_BF16(c[i][j], Al[i][0], Al[i][1], Al[i][2], Al[i][3], Bh[j][0], Bh[j][1]);
                }
        }
    }

    #pragma unroll
    for (int i = 0; i < 2; i++) {
        int R0 = m0 + i * 16 + g, R1 = R0 + 8;
        #pragma unroll
        for (int j = 0; j < 2; j++) {
            int Cc = n0 + nb + j * 8 + tg * 2;
            atomicAdd(&g_h1f[(size_t)R0 * FF + Cc],     c[i][j][0]);
            atomicAdd(&g_h1f[(size_t)R0 * FF + Cc + 1], c[i][j][1]);
            atomicAdd(&g_h1f[(size_t)R1 * FF + Cc],     c[i][j][2]);
            atomicAdd(&g_h1f[(size_t)R1 * FF + Cc + 1], c[i][j][3]);
        }
    }
}

// ====== GEMM2: g_h2 += h1 @ W2^T.  Double-buffered, 1 barrier/chunk ======
__global__ __launch_bounds__(256) void gemm2_kernel(const float* __restrict__ W2) {
    extern __shared__ __align__(128) unsigned char smd[];
    const int SAHI = 0, SALO = 10240, SBHI = 20480, SBLO = 25600;

    int tid = threadIdx.x, wid = tid >> 5, lane = tid & 31;
    int g = lane >> 2, tg = lane & 3;
    int wm = wid >> 1, wn = wid & 1;
    int m0 = wm * 32, nb = wn * 32;
    int n0 = blockIdx.x * 64;
    int k0 = blockIdx.y * (3 * KC);

    int lrow = lane & 7;
    int amOff = ((lane >> 3) & 1) * 8 + lrow;
    int akOff = (lane >> 4) * 16;
    int bnOff = (lane >> 4) * 8 + lrow;
    int bkOff = ((lane >> 3) & 1) * 16;

    int ar = tid >> 1, ah = tid & 1;
    int br[2], bq[2];
    #pragma unroll
    for (int t = 0; t < 2; t++) { int idx = tid + t * 256; br[t] = idx >> 3; bq[t] = idx & 7; }

    float c[2][4][4];
    #pragma unroll
    for (int i = 0; i < 2; i++)
        #pragma unroll
        for (int j = 0; j < 4; j++)
            #pragma unroll
            for (int r = 0; r < 4; r++) c[i][j][r] = 0.f;

    const float* pA = g_h1f + (size_t)ar * FF + k0 + ah * 16;

    float4 av[4];
    #pragma unroll
    for (int t = 0; t < 4; t++) av[t] = ((const float4*)pA)[t];
    float4 bv[2];
    #pragma unroll
    for (int t = 0; t < 2; t++)
        bv[t] = *(const float4*)(W2 + (size_t)(n0 + br[t]) * FF + k0 + bq[t] * 4);

    for (int ch = 0; ch < 3; ch++) {
        unsigned char* sm = smd + (ch & 1) * G2_BUF;
        store_a_chunk(sm, SAHI, SALO, ar, ah, av);
        #pragma unroll
        for (int t = 0; t < 2; t++) {
            unsigned long long hi, lo;
            split4(bv[t], hi, lo);
            int boff = br[t] * RS + bq[t] * 8;
            *(unsigned long long*)(sm + SBHI + boff) = hi;
            *(unsigned long long*)(sm + SBLO + boff) = lo;
        }
        __syncthreads();     // single barrier: double buffer protects next store

        if (ch + 1 < 3) {
            int kk = (ch + 1) * KC;
            #pragma unroll
            for (int t = 0; t < 4; t++) av[t] = ((const float4*)(pA + kk))[t];
            #pragma unroll
            for (int t = 0; t < 2; t++)
                bv[t] = *(const float4*)(W2 + (size_t)(n0 + br[t]) * FF + k0 + kk + bq[t] * 4);
        }

        #pragma unroll
        for (int ks = 0; ks < 2; ks++) {
            unsigned Ah[2][4], Al[2][4], Bh[4][2], Bl[4][2];
            #pragma unroll
            for (int i = 0; i < 2; i++) {
                int off = (m0 + i * 16 + amOff) * RS + ks * 32 + akOff;
                ldm_x4(Ah[i][0], Ah[i][1], Ah[i][2], Ah[i][3], sm + SAHI + off);
                ldm_x4(Al[i][0], Al[i][1], Al[i][2], Al[i][3], sm + SALO + off);
            }
            #pragma unroll
            for (int jb = 0; jb < 4; jb += 2) {
                int off = (nb + jb * 8 + bnOff) * RS + ks * 32 + bkOff;
                ldm_x4(Bh[jb][0], Bh[jb][1], Bh[jb + 1][0], Bh[jb + 1][1], sm + SBHI + off);
                ldm_x4(Bl[jb][0], Bl[jb][1], Bl[jb + 1][0], Bl[jb + 1][1], sm + SBLO + off);
            }
            #pragma unroll
            for (int i = 0; i < 2; i++)
                #pragma unroll
                for (int j = 0; j < 4; j++) {
                    MMA_BF16(c[i][j], Ah[i][0], Ah[i][1], Ah[i][2], Ah[i][3], Bh[j][0], Bh[j][1]);
                    MMA_BF16(c[i][j], Ah[i][0], Ah[i][1], Ah[i][2], Ah[i][3], Bl[j][0], Bl[j][1]);
                    MMA_BF16(c[i][j], Al[i][0], Al[i][1], Al[i][2], Al[i][3], Bh[j][0], Bh[j][1]);
                }
        }
    }

    #pragma unroll
    for (int i = 0; i < 2; i++) {
        int R0 = m0 + i * 16 + g, R1 = R0 + 8;
        #pragma unroll
        for (int j = 0; j < 4; j++) {
            int Cc = n0 + nb + j * 8 + tg * 2;
            atomicAdd(&g_h2[(size_t)R0 * HIDDEN + Cc],     c[i][j][0]);
            atomicAdd(&g_h2[(size_t)R0 * HIDDEN + Cc + 1], c[i][j][1]);
            atomicAdd(&g_h2[(size_t)R1 * HIDDEN + Cc],     c[i][j][2]);
            atomicAdd(&g_h2[(size_t)R1 * HIDDEN + Cc + 1], c[i][j][3]);
        }
    }
}

// ---------------- L2 normalize rows ----------------
__global__ __launch_bounds__(192) void norm_kernel(float* __restrict__ out) {
    int s = blockIdx.x, tid = threadIdx.x;
    float4 acc = ((const float4*)(g_h2 + s * HIDDEN))[tid];
    float ss = acc.x * acc.x + acc.y * acc.y + acc.z * acc.z + acc.w * acc.w;

    __shared__ float red[6];
    #pragma unroll
    for (int o = 16; o > 0; o >>= 1) ss += __shfl_xor_sync(0xffffffffu, ss, o);
    if ((tid & 31) == 0) red[tid >> 5] = ss;
    __syncthreads();
    __shared__ float sInv;
    if (tid == 0) {
        float tot = 0.f;
        #pragma unroll
        for (int w = 0; w < 6; w++) tot += red[w];
        sInv = 1.0f / fmaxf(sqrtf(tot), 1e-12f);
    }
    __syncthreads();
    float inv = sInv;
    float4 r = make_float4(acc.x * inv, acc.y * inv, acc.z * inv, acc.w * inv);
    ((float4*)(out + s * HIDDEN))[tid] = r;
}

// ---------------- launch ----------------
extern "C" void kernel_launch(void* const* d_in, const int* in_sizes, int n_in,
                              void* d_out, int out_size) {
    const float* hs   = (const float*)d_in[0];   // [65536, 768] fp32
    const int*   lens = (const int*)  d_in[1];   // [128] int32
    const float* W1   = (const float*)d_in[2];   // [3072, 768] fp32
    const float* W2   = (const float*)d_in[3];   // [768, 3072] fp32
    float* out = (float*)d_out;                  // [128, 768] fp32

    void* pMeans = 0;
    cudaGetSymbolAddress(&pMeans, g_means);
    cudaMemsetAsync(pMeans, 0, NSEQ * HIDDEN * sizeof(float));

    cudaFuncSetAttribute(gemm1_kernel, cudaFuncAttributeMaxDynamicSharedMemorySize, 2 * G1_BUF);
    cudaFuncSetAttribute(gemm2_kernel, cudaFuncAttributeMaxDynamicSharedMemorySize, 2 * G2_BUF);

    pool_kernel<<<TOKENS / TOKB, 192>>>(hs, lens);
    gemm1_kernel<<<dim3(FF / 32, SPLIT1), 256, 2 * G1_BUF>>>(W1);
    gemm2_kernel<<<dim3(HIDDEN / 64, SPLIT2), 256, 2 * G2_BUF>>>(W2);
    norm_kernel<<<NSEQ, 192>>>(out);
}